// round 1
// baseline (speedup 1.0000x reference)
#include <cuda_runtime.h>

// HardNetLoss: x (16384 x 256) row-normalized fp32.
// cnt = 8192. S = A @ P^T (A = x[:cnt], P = x[cnt:]).
// d_ij = sqrt((1 - s_ij + eps)*2)  -> monotone decreasing in s.
// neg_i = min over (col i mins, row i mins) excluding diag  <=>  max s over row i / col i excl diag.
// loss = mean(relu(1 - neg + pos)), pos_i = d_ii.

#define CNT 8192
#define KDIM 256
#define BM 128
#define BN 128
#define BK 32
#define TM 8
#define TN 8
#define EPSV 1e-6f

// scratch (device globals; no allocation allowed)
__device__ unsigned g_rowmax[CNT];
__device__ unsigned g_colmax[CNT];
__device__ float    g_diag[CNT];
__device__ float    g_partial[CNT / 256];

// order-preserving float <-> uint encoding (for atomicMax on floats incl. negatives)
__device__ __forceinline__ unsigned encf(float f) {
    unsigned u = __float_as_uint(f);
    return (u & 0x80000000u) ? ~u : (u | 0x80000000u);
}
__device__ __forceinline__ float decf(unsigned e) {
    unsigned u = (e & 0x80000000u) ? (e & 0x7fffffffu) : ~e;
    return __uint_as_float(u);
}

__global__ void init_kernel() {
    int i = blockIdx.x * blockDim.x + threadIdx.x;
    if (i < CNT) {
        g_rowmax[i] = 0u;   // 0 is the minimum of the encoded order -> identity for max
        g_colmax[i] = 0u;
    }
}

__global__ __launch_bounds__(256, 2)
void gemm_max_kernel(const float* __restrict__ A, const float* __restrict__ P) {
    __shared__ float As[BK][BM];   // transposed: As[k][m]
    __shared__ float Bs[BK][BN];   // transposed: Bs[k][n]
    __shared__ unsigned srow[BM];
    __shared__ unsigned scol[BN];

    const int tid = threadIdx.x;
    const int tx = tid & 15;       // 16 threads along N
    const int ty = tid >> 4;       // 16 threads along M
    const int bx = blockIdx.x;     // N tile
    const int by = blockIdx.y;     // M tile

    float acc[TM][TN];
#pragma unroll
    for (int i = 0; i < TM; i++)
#pragma unroll
        for (int j = 0; j < TN; j++) acc[i][j] = 0.0f;

    const float4* A4 = reinterpret_cast<const float4*>(A);
    const float4* B4 = reinterpret_cast<const float4*>(P);
    const int row_f4 = KDIM / 4;   // 64 float4 per row

    for (int k0 = 0; k0 < KDIM; k0 += BK) {
        // cooperative load: 128 rows x 32 k-cols, both operands, float4 coalesced
#pragma unroll
        for (int l = 0; l < 4; l++) {
            int idx = tid + l * 256;       // 0..1023
            int row = idx >> 3;            // 0..127
            int c4  = idx & 7;             // 0..7 (float4 within the 32-wide k chunk)
            float4 va = A4[(size_t)(by * BM + row) * row_f4 + (k0 >> 2) + c4];
            As[c4 * 4 + 0][row] = va.x;
            As[c4 * 4 + 1][row] = va.y;
            As[c4 * 4 + 2][row] = va.z;
            As[c4 * 4 + 3][row] = va.w;
            float4 vb = B4[(size_t)(bx * BN + row) * row_f4 + (k0 >> 2) + c4];
            Bs[c4 * 4 + 0][row] = vb.x;
            Bs[c4 * 4 + 1][row] = vb.y;
            Bs[c4 * 4 + 2][row] = vb.z;
            Bs[c4 * 4 + 3][row] = vb.w;
        }
        __syncthreads();

#pragma unroll
        for (int kk = 0; kk < BK; kk++) {
            float ar[TM], br[TN];
            *reinterpret_cast<float4*>(&ar[0]) = *reinterpret_cast<const float4*>(&As[kk][ty * TM]);
            *reinterpret_cast<float4*>(&ar[4]) = *reinterpret_cast<const float4*>(&As[kk][ty * TM + 4]);
            *reinterpret_cast<float4*>(&br[0]) = *reinterpret_cast<const float4*>(&Bs[kk][tx * TN]);
            *reinterpret_cast<float4*>(&br[4]) = *reinterpret_cast<const float4*>(&Bs[kk][tx * TN + 4]);
#pragma unroll
            for (int i = 0; i < TM; i++)
#pragma unroll
                for (int j = 0; j < TN; j++)
                    acc[i][j] = fmaf(ar[i], br[j], acc[i][j]);
        }
        __syncthreads();
    }

    // fused epilogue: per-row / per-col max of S excluding diagonal, capture diagonal
    if (tid < BM) { srow[tid] = 0u; scol[tid] = 0u; }
    __syncthreads();

    const int grow0 = by * BM + ty * TM;
    const int gcol0 = bx * BN + tx * TN;

    float rmax[TM], cmax[TN];
#pragma unroll
    for (int i = 0; i < TM; i++) rmax[i] = -2.0f;
#pragma unroll
    for (int j = 0; j < TN; j++) cmax[j] = -2.0f;

#pragma unroll
    for (int i = 0; i < TM; i++) {
#pragma unroll
        for (int j = 0; j < TN; j++) {
            float s = acc[i][j];
            if (grow0 + i == gcol0 + j) {
                g_diag[grow0 + i] = s;      // unique writer
            } else {
                rmax[i] = fmaxf(rmax[i], s);
                cmax[j] = fmaxf(cmax[j], s);
            }
        }
    }
#pragma unroll
    for (int i = 0; i < TM; i++) atomicMax(&srow[ty * TM + i], encf(rmax[i]));
#pragma unroll
    for (int j = 0; j < TN; j++) atomicMax(&scol[tx * TN + j], encf(cmax[j]));
    __syncthreads();

    if (tid < BM) {
        atomicMax(&g_rowmax[by * BM + tid], srow[tid]);
    } else {
        int t = tid - BM;
        atomicMax(&g_colmax[bx * BN + t], scol[t]);
    }
}

__global__ void finish_kernel() {
    __shared__ float red[256];
    int i = blockIdx.x * 256 + threadIdx.x;
    float smax = fmaxf(decf(g_rowmax[i]), decf(g_colmax[i]));
    float neg = sqrtf((1.0f - smax + EPSV) * 2.0f);
    float pos = sqrtf((1.0f - g_diag[i] + EPSV) * 2.0f);
    float t = fmaxf(1.0f - neg + pos, 0.0f);
    red[threadIdx.x] = t;
    __syncthreads();
#pragma unroll
    for (int s = 128; s > 0; s >>= 1) {
        if (threadIdx.x < s) red[threadIdx.x] += red[threadIdx.x + s];
        __syncthreads();
    }
    if (threadIdx.x == 0) g_partial[blockIdx.x] = red[0];
}

__global__ void final_kernel(float* __restrict__ out) {
    if (threadIdx.x == 0) {
        float s = 0.0f;
        for (int i = 0; i < CNT / 256; i++) s += g_partial[i];
        out[0] = s / (float)CNT;
    }
}

extern "C" void kernel_launch(void* const* d_in, const int* in_sizes, int n_in,
                              void* d_out, int out_size) {
    (void)in_sizes; (void)n_in; (void)out_size;
    const float* x = (const float*)d_in[0];
    const float* A = x;                        // first cnt rows
    const float* P = x + (size_t)CNT * KDIM;   // last cnt rows
    float* out = (float*)d_out;

    init_kernel<<<CNT / 256, 256>>>();
    dim3 grid(CNT / BN, CNT / BM);
    gemm_max_kernel<<<grid, 256>>>(A, P);
    finish_kernel<<<CNT / 256, 256>>>();
    final_kernel<<<1, 32>>>(out);
}